// round 1
// baseline (speedup 1.0000x reference)
#include <cuda_runtime.h>
#include <cuda_bf16.h>
#include <cstdint>

#define N_TOK 1024
#define DH    64
#define NB    8     // batch
#define NGH   4     // global heads
#define NLH   8     // local heads
#define NLVL  4     // mask levels
#define NN    (N_TOK * N_TOK)   // 1048576

// Scratch for S[b,g,q,k] = QK^T scores: 8*4*1024*1024 floats = 128 MB.
// __device__ global array (module-load allocation, permitted by harness rules).
__device__ float g_S[(size_t)NB * NGH * N_TOK * N_TOK];

// ---------------------------------------------------------------------------
// Kernel 1: S[bg,q,k] = sum_d q[bg,q,d] * k[bg,k,d]
// 128x128 tile per CTA, 8x8 micro-tile per thread, D chunked 2x32 in smem.
// Smem tiles stored TRANSPOSED (Qs[d][row]) so the inner loop does
// conflict-free broadcast/contiguous LDS.128 reads.
// ---------------------------------------------------------------------------
__global__ __launch_bounds__(256)
void qk_gemm_kernel(const float* __restrict__ q, const float* __restrict__ k)
{
    __shared__ float Qs[32][132];   // [d][row], pad 132 keeps 16B alignment, spreads banks
    __shared__ float Ks[32][132];

    const int bg = blockIdx.z;                 // 0..31 = b*4+g
    const int qt = blockIdx.y * 128;
    const int kt = blockIdx.x * 128;
    const int tid = threadIdx.x;
    const int tx = tid & 15;                   // k sub-tile (8 cols)
    const int ty = tid >> 4;                   // q sub-tile (8 rows)

    const float* __restrict__ qb = q + ((size_t)bg * N_TOK + qt) * DH;
    const float* __restrict__ kb = k + ((size_t)bg * N_TOK + kt) * DH;

    float acc[8][8];
#pragma unroll
    for (int i = 0; i < 8; i++)
#pragma unroll
        for (int j = 0; j < 8; j++) acc[i][j] = 0.0f;

#pragma unroll 1
    for (int chunk = 0; chunk < 2; chunk++) {
        // --- stage: load 128 rows x 32 d of Q and K tiles, transposed ---
#pragma unroll
        for (int r = 0; r < 4; r++) {
            int idx = r * 256 + tid;           // 0..1023
            int row = idx >> 3;                // 0..127
            int d4  = idx & 7;                 // 0..7 -> 4 floats each
            const float* qg = qb + (size_t)row * DH + chunk * 32 + d4 * 4;
            const float* kg = kb + (size_t)row * DH + chunk * 32 + d4 * 4;
            float4 qv = *(const float4*)qg;
            float4 kv = *(const float4*)kg;
            Qs[d4 * 4 + 0][row] = qv.x;
            Qs[d4 * 4 + 1][row] = qv.y;
            Qs[d4 * 4 + 2][row] = qv.z;
            Qs[d4 * 4 + 3][row] = qv.w;
            Ks[d4 * 4 + 0][row] = kv.x;
            Ks[d4 * 4 + 1][row] = kv.y;
            Ks[d4 * 4 + 2][row] = kv.z;
            Ks[d4 * 4 + 3][row] = kv.w;
        }
        __syncthreads();

        // --- compute: 32 d-steps, 64 FMA per step per thread ---
#pragma unroll
        for (int d = 0; d < 32; d++) {
            float4 qa = *(const float4*)&Qs[d][ty * 8];
            float4 qc = *(const float4*)&Qs[d][ty * 8 + 4];
            float4 ka = *(const float4*)&Ks[d][tx * 8];
            float4 kc = *(const float4*)&Ks[d][tx * 8 + 4];
            float qv[8] = {qa.x, qa.y, qa.z, qa.w, qc.x, qc.y, qc.z, qc.w};
            float kv[8] = {ka.x, ka.y, ka.z, ka.w, kc.x, kc.y, kc.z, kc.w};
#pragma unroll
            for (int i = 0; i < 8; i++)
#pragma unroll
                for (int j = 0; j < 8; j++)
                    acc[i][j] = fmaf(qv[i], kv[j], acc[i][j]);
        }
        __syncthreads();
    }

    // --- store 8x8 micro-tile, vectorized float4 ---
    float* __restrict__ Sp = g_S + (size_t)bg * NN;
#pragma unroll
    for (int i = 0; i < 8; i++) {
        int qrow = qt + ty * 8 + i;
        float* o = Sp + (size_t)qrow * N_TOK + kt + tx * 8;
        *(float4*)(o)     = make_float4(acc[i][0], acc[i][1], acc[i][2], acc[i][3]);
        *(float4*)(o + 4) = make_float4(acc[i][4], acc[i][5], acc[i][6], acc[i][7]);
    }
}

// ---------------------------------------------------------------------------
// Kernel 2: epilogue. One thread per (q,k); handles all 8 batches so the
// mask_weights computation (128 FMA) is amortized 8x.
//   mw[g,h]   = sum_l masks[q,k,l] * proj[l, g*8+h]
//   v[h]      = relu( sum_g S[b,g,q,k] * mw[g,h] )
//   out[b,h]  = sum_h' v[h'] * W[h,h'] + bias[h]     (layout [B,LH,Nq,Nk])
// ---------------------------------------------------------------------------
__global__ __launch_bounds__(256)
void epilogue_kernel(const float* __restrict__ masks,
                     const float* __restrict__ proj,   // [4, 32]
                     const float* __restrict__ hw,     // [8, 8]  (out, in)
                     const float* __restrict__ hb,     // [8]
                     float* __restrict__ out)
{
    __shared__ float sP[NLVL * NGH * NLH];   // 128
    __shared__ float sW[NLH * NLH];          // 64
    __shared__ float sB[NLH];                // 8

    const int tid = threadIdx.x;
    if (tid < 128) sP[tid] = proj[tid];
    if (tid < 64)  sW[tid] = hw[tid];
    if (tid < 8)   sB[tid] = hb[tid];
    __syncthreads();

    const size_t i = (size_t)blockIdx.x * 256 + tid;   // 0 .. N*N-1

    // masks[q,k,0..3] contiguous -> one float4
    float4 m = *(const float4*)(masks + 4 * i);

    float mw[NGH * NLH];
#pragma unroll
    for (int x = 0; x < 32; x++) {
        float t = m.x * sP[x];
        t = fmaf(m.y, sP[32 + x], t);
        t = fmaf(m.z, sP[64 + x], t);
        t = fmaf(m.w, sP[96 + x], t);
        mw[x] = t;
    }

    const float* __restrict__ Sp = g_S + i;

#pragma unroll
    for (int b = 0; b < NB; b++) {
        float s0 = Sp[((size_t)(b * 4 + 0)) << 20];
        float s1 = Sp[((size_t)(b * 4 + 1)) << 20];
        float s2 = Sp[((size_t)(b * 4 + 2)) << 20];
        float s3 = Sp[((size_t)(b * 4 + 3)) << 20];

        float v[NLH];
#pragma unroll
        for (int h = 0; h < NLH; h++) {
            float t = s0 * mw[h];
            t = fmaf(s1, mw[8 + h], t);
            t = fmaf(s2, mw[16 + h], t);
            t = fmaf(s3, mw[24 + h], t);
            v[h] = fmaxf(t, 0.0f);
        }
#pragma unroll
        for (int h = 0; h < NLH; h++) {
            float o = sB[h];
#pragma unroll
            for (int hh = 0; hh < NLH; hh++)
                o = fmaf(v[hh], sW[h * 8 + hh], o);
            out[((size_t)(b * 8 + h) << 20) + i] = o;
        }
    }
}

extern "C" void kernel_launch(void* const* d_in, const int* in_sizes, int n_in,
                              void* d_out, int out_size)
{
    const float* q     = (const float*)d_in[0];   // [8,4,1024,64]
    const float* k     = (const float*)d_in[1];   // [8,4,1024,64]
    const float* masks = (const float*)d_in[2];   // [1024,1024,4]
    const float* proj  = (const float*)d_in[3];   // [4,32]
    const float* hw    = (const float*)d_in[4];   // [8,8]
    const float* hb    = (const float*)d_in[5];   // [8]
    float* out = (float*)d_out;                   // [8,8,1024,1024]

    dim3 g1(N_TOK / 128, N_TOK / 128, NB * NGH);  // (8,8,32)
    qk_gemm_kernel<<<g1, 256>>>(q, k);

    epilogue_kernel<<<NN / 256, 256>>>(masks, proj, hw, hb, out);
}

// round 3
// speedup vs baseline: 1.3877x; 1.3877x over previous
#include <cuda_runtime.h>
#include <cuda_bf16.h>
#include <cstdint>

#define N_TOK 1024
#define DH    64
#define NB    8
#define NGH   4
#define NLH   8
#define NLVL  4
#define NN    (N_TOK * N_TOK)
#define NBG   (NB * NGH)          // 32
#define KSPLIT 192                // 64 hi·hi + 64 hi·lo + 64 lo·hi
#define KSTEPS 12                 // 192 / 16
#define SROW   200                // padded smem row stride (bf16): 400B -> conflict-free ldmatrix

// ---------------- scratch (__device__ globals: allocation-free) ------------
__device__ float g_S[(size_t)NBG * NN];                       // 128 MB
__device__ __nv_bfloat16 g_A[(size_t)NBG * N_TOK * KSPLIT];   // 12.6 MB
__device__ __nv_bfloat16 g_B[(size_t)NBG * N_TOK * KSPLIT];   // 12.6 MB

__device__ __forceinline__ uint32_t smem_u32(const void* p) {
    uint32_t a;
    asm("{ .reg .u64 t; cvta.to.shared.u64 t, %1; cvt.u32.u64 %0, t; }" : "=r"(a) : "l"(p));
    return a;
}

// ---------------------------------------------------------------------------
// Kernel 0: split q,k fp32 -> bf16 hi/lo, concatenated along K:
//   A[row, 0:64]=q_hi  A[row,64:128]=q_hi  A[row,128:192]=q_lo
//   B[row, 0:64]=k_hi  B[row,64:128]=k_lo  B[row,128:192]=k_hi
// => A·B^T = hi·hi + hi·lo + lo·hi  (lo·lo dropped, ~1e-5 rel)
// ---------------------------------------------------------------------------
__global__ __launch_bounds__(256)
void split_kernel(const float* __restrict__ q, const float* __restrict__ k)
{
    size_t i = (size_t)blockIdx.x * 256 + threadIdx.x;   // over NBG*1024*64
    int d = (int)(i & 63);
    size_t rb = (i >> 6) * KSPLIT;

    float qv = q[i], kv = k[i];
    __nv_bfloat16 qh = __float2bfloat16(qv);
    __nv_bfloat16 kh = __float2bfloat16(kv);
    __nv_bfloat16 ql = __float2bfloat16(qv - __bfloat162float(qh));
    __nv_bfloat16 kl = __float2bfloat16(kv - __bfloat162float(kh));

    g_A[rb + d]       = qh;
    g_A[rb + 64 + d]  = qh;
    g_A[rb + 128 + d] = ql;
    g_B[rb + d]       = kh;
    g_B[rb + 64 + d]  = kl;
    g_B[rb + 128 + d] = kh;
}

// ---------------------------------------------------------------------------
// Kernel 1: mma.sync bf16 GEMM.  S[bg, qt:qt+128, kt:kt+128] = A·B^T (K=192)
// CTA: 128x128 tile, 256 threads = 8 warps in 2x4 grid, warp tile 64x32.
// Full K staged in smem with padded rows (SROW=200 bf16) -> every ldmatrix
// row address lands on a distinct 16B sub-bank (i*400 % 128 = i*16).
// ---------------------------------------------------------------------------
#define SM_BYTES (2 * 128 * SROW * 2)    // 102400

__global__ __launch_bounds__(256)
void qk_gemm_mma(const __nv_bfloat16* __restrict__ A,
                 const __nv_bfloat16* __restrict__ B)
{
    extern __shared__ __align__(16) char smem[];
    __nv_bfloat16* As = (__nv_bfloat16*)smem;          // [128][SROW]
    __nv_bfloat16* Bs = As + 128 * SROW;

    const int tid  = threadIdx.x;
    const int lane = tid & 31;
    const int w    = tid >> 5;
    const int wm   = (w & 1) * 64;     // warp m offset
    const int wn   = (w >> 1) * 32;    // warp n offset

    const int bg = blockIdx.z;
    const int qt = blockIdx.y * 128;
    const int kt = blockIdx.x * 128;

    const __nv_bfloat16* Ag = A + ((size_t)bg * N_TOK + qt) * KSPLIT;
    const __nv_bfloat16* Bg = B + ((size_t)bg * N_TOK + kt) * KSPLIT;

    // --- stage both tiles: 128 rows x 192 bf16, as 24 uint4 per row ---
#pragma unroll
    for (int it = 0; it < 12; it++) {
        int idx = it * 256 + tid;          // 0..3071
        int row = idx / 24;
        int c8  = (idx % 24) * 8;          // bf16 col, multiple of 8
        *(uint4*)(As + row * SROW + c8) = *(const uint4*)(Ag + (size_t)row * KSPLIT + c8);
        *(uint4*)(Bs + row * SROW + c8) = *(const uint4*)(Bg + (size_t)row * KSPLIT + c8);
    }
    __syncthreads();

    const uint32_t a_base = smem_u32(As);
    const uint32_t b_base = smem_u32(Bs);

    // per-thread ldmatrix row/k offsets
    const int arow  = lane & 15;             // A x4: rows 0..15, k half by lane>>4
    const int akoff = (lane >> 4) * 8;
    const int brow  = lane & 7;              // B x2: rows 0..7, k half by bit3
    const int bkoff = ((lane >> 3) & 1) * 8;

    float acc[4][4][4];
#pragma unroll
    for (int mi = 0; mi < 4; mi++)
#pragma unroll
        for (int ni = 0; ni < 4; ni++)
#pragma unroll
            for (int r = 0; r < 4; r++) acc[mi][ni][r] = 0.0f;

#pragma unroll
    for (int s = 0; s < KSTEPS; s++) {
        const int k0 = s * 16;
        uint32_t af[4][4], bf[4][2];
#pragma unroll
        for (int mi = 0; mi < 4; mi++) {
            uint32_t addr = a_base + (uint32_t)(((wm + mi * 16 + arow) * SROW + k0 + akoff) * 2);
            asm volatile("ldmatrix.sync.aligned.m8n8.x4.shared.b16 {%0,%1,%2,%3}, [%4];"
                         : "=r"(af[mi][0]), "=r"(af[mi][1]), "=r"(af[mi][2]), "=r"(af[mi][3])
                         : "r"(addr));
        }
#pragma unroll
        for (int ni = 0; ni < 4; ni++) {
            uint32_t addr = b_base + (uint32_t)(((wn + ni * 8 + brow) * SROW + k0 + bkoff) * 2);
            asm volatile("ldmatrix.sync.aligned.m8n8.x2.shared.b16 {%0,%1}, [%2];"
                         : "=r"(bf[ni][0]), "=r"(bf[ni][1])
                         : "r"(addr));
        }
#pragma unroll
        for (int mi = 0; mi < 4; mi++)
#pragma unroll
            for (int ni = 0; ni < 4; ni++) {
                asm volatile(
                    "mma.sync.aligned.m16n8k16.row.col.f32.bf16.bf16.f32 "
                    "{%0,%1,%2,%3}, {%4,%5,%6,%7}, {%8,%9}, {%0,%1,%2,%3};"
                    : "+f"(acc[mi][ni][0]), "+f"(acc[mi][ni][1]),
                      "+f"(acc[mi][ni][2]), "+f"(acc[mi][ni][3])
                    : "r"(af[mi][0]), "r"(af[mi][1]), "r"(af[mi][2]), "r"(af[mi][3]),
                      "r"(bf[ni][0]), "r"(bf[ni][1]));
            }
    }

    // --- store: c0,c1 -> (m, n..n+1); c2,c3 -> (m+8, n..n+1) ---
    float* __restrict__ Sp = g_S + (size_t)bg * NN;
#pragma unroll
    for (int mi = 0; mi < 4; mi++) {
#pragma unroll
        for (int ni = 0; ni < 4; ni++) {
            int m = qt + wm + mi * 16 + (lane >> 2);
            int n = kt + wn + ni * 8 + (lane & 3) * 2;
            *(float2*)(Sp + (size_t)m * N_TOK + n)       = make_float2(acc[mi][ni][0], acc[mi][ni][1]);
            *(float2*)(Sp + (size_t)(m + 8) * N_TOK + n) = make_float2(acc[mi][ni][2], acc[mi][ni][3]);
        }
    }
}

// ---------------------------------------------------------------------------
// Kernel 2: epilogue. One thread per (q,k); all 8 batches per thread.
// ---------------------------------------------------------------------------
__global__ __launch_bounds__(256, 4)
void epilogue_kernel(const float* __restrict__ masks,
                     const float* __restrict__ proj,
                     const float* __restrict__ hw,
                     const float* __restrict__ hb,
                     float* __restrict__ out)
{
    __shared__ float sP[NLVL * NGH * NLH];
    __shared__ float sW[NLH * NLH];
    __shared__ float sB[NLH];

    const int tid = threadIdx.x;
    if (tid < 128) sP[tid] = proj[tid];
    if (tid < 64)  sW[tid] = hw[tid];
    if (tid < 8)   sB[tid] = hb[tid];
    __syncthreads();

    const size_t i = (size_t)blockIdx.x * 256 + tid;
    float4 m = *(const float4*)(masks + 4 * i);

    float mw[NGH * NLH];
#pragma unroll
    for (int x = 0; x < 32; x++) {
        float t = m.x * sP[x];
        t = fmaf(m.y, sP[32 + x], t);
        t = fmaf(m.z, sP[64 + x], t);
        t = fmaf(m.w, sP[96 + x], t);
        mw[x] = t;
    }

    const float* __restrict__ Sp = g_S + i;

#pragma unroll
    for (int b = 0; b < NB; b++) {
        float s0 = Sp[((size_t)(b * 4 + 0)) << 20];
        float s1 = Sp[((size_t)(b * 4 + 1)) << 20];
        float s2 = Sp[((size_t)(b * 4 + 2)) << 20];
        float s3 = Sp[((size_t)(b * 4 + 3)) << 20];

        float v[NLH];
#pragma unroll
        for (int h = 0; h < NLH; h++) {
            float t = s0 * mw[h];
            t = fmaf(s1, mw[8 + h], t);
            t = fmaf(s2, mw[16 + h], t);
            t = fmaf(s3, mw[24 + h], t);
            v[h] = fmaxf(t, 0.0f);
        }
#pragma unroll
        for (int h = 0; h < NLH; h++) {
            float o = sB[h];
#pragma unroll
            for (int hh = 0; hh < NLH; hh++)
                o = fmaf(v[hh], sW[h * 8 + hh], o);
            out[((size_t)(b * 8 + h) << 20) + i] = o;
        }
    }
}

extern "C" void kernel_launch(void* const* d_in, const int* in_sizes, int n_in,
                              void* d_out, int out_size)
{
    const float* q     = (const float*)d_in[0];
    const float* k     = (const float*)d_in[1];
    const float* masks = (const float*)d_in[2];
    const float* proj  = (const float*)d_in[3];
    const float* hw    = (const float*)d_in[4];
    const float* hb    = (const float*)d_in[5];
    float* out = (float*)d_out;

    cudaFuncSetAttribute(qk_gemm_mma, cudaFuncAttributeMaxDynamicSharedMemorySize, SM_BYTES);

    split_kernel<<<(NBG * N_TOK * DH) / 256, 256>>>(q, k);

    __nv_bfloat16 *gA, *gB;
    cudaGetSymbolAddress((void**)&gA, g_A);
    cudaGetSymbolAddress((void**)&gB, g_B);
    dim3 g1(N_TOK / 128, N_TOK / 128, NBG);
    qk_gemm_mma<<<g1, 256, SM_BYTES>>>(gA, gB);

    epilogue_kernel<<<NN / 256, 256>>>(masks, proj, hw, hb, out);
}

// round 4
// speedup vs baseline: 1.7033x; 1.2274x over previous
#include <cuda_runtime.h>
#include <cuda_bf16.h>
#include <cuda_fp16.h>
#include <cstdint>

#define N_TOK 1024
#define DH    64
#define NB    8
#define NGH   4
#define NLH   8
#define NLVL  4
#define NN    (N_TOK * N_TOK)
#define NBG   (NB * NGH)          // 32
#define KSTEPS 12                 // 3 x (K=64) split terms, 16 per MMA step
#define SROW   136                // padded smem row stride (bf16): 272B -> conflict-free ldmatrix

// ---------------- scratch (__device__ global: allocation-free) -------------
__device__ __half g_S[(size_t)NBG * NN];                      // 64 MB

__device__ __forceinline__ uint32_t smem_u32(const void* p) {
    uint32_t a;
    asm("{ .reg .u64 t; cvta.to.shared.u64 t, %1; cvt.u32.u64 %0, t; }" : "=r"(a) : "l"(p));
    return a;
}

// ---------------------------------------------------------------------------
// Kernel 1: fused split + mma.sync bf16 GEMM.
//   S[bg, qt:+128, kt:+128] = qk_hi·kh_hi + qk_hi·kh_lo + qk_lo·kh_hi
// Staging converts fp32 q/k -> bf16 hi/lo in-register:
//   As[row, 0:64] = q_hi, As[row, 64:128] = q_lo   (same for Bs with k)
// K-step s: 0-3 (hi,hi), 4-7 (hi,lo), 8-11 (lo,hi)  via block offsets.
// CTA: 128x128 tile, 256 thr = 8 warps (2x4), warp tile 64x32.
// ---------------------------------------------------------------------------
#define SM_BYTES (2 * 128 * SROW * 2)    // 69632

__global__ __launch_bounds__(256)
void qk_gemm_mma(const float* __restrict__ q, const float* __restrict__ k)
{
    extern __shared__ __align__(16) char smem[];
    __nv_bfloat16* As = (__nv_bfloat16*)smem;          // [128][SROW]
    __nv_bfloat16* Bs = As + 128 * SROW;

    const int tid  = threadIdx.x;
    const int lane = tid & 31;
    const int w    = tid >> 5;
    const int wm   = (w & 1) * 64;
    const int wn   = (w >> 1) * 32;

    const int bg = blockIdx.z;
    const int qt = blockIdx.y * 128;
    const int kt = blockIdx.x * 128;

    const float* Qg = q + ((size_t)bg * N_TOK + qt) * DH;
    const float* Kg = k + ((size_t)bg * N_TOK + kt) * DH;

    // --- stage + convert: 128 rows x 64 fp32 -> hi|lo bf16 (128 cols) ---
#pragma unroll
    for (int it = 0; it < 8; it++) {
        int idx = it * 256 + tid;          // 0..2047
        int row = idx >> 4;
        int c4  = (idx & 15) * 4;
        float4 qv = *(const float4*)(Qg + (size_t)row * DH + c4);
        float4 kv = *(const float4*)(Kg + (size_t)row * DH + c4);

        __nv_bfloat16 qh0 = __float2bfloat16(qv.x), qh1 = __float2bfloat16(qv.y);
        __nv_bfloat16 qh2 = __float2bfloat16(qv.z), qh3 = __float2bfloat16(qv.w);
        __nv_bfloat16 ql0 = __float2bfloat16(qv.x - __bfloat162float(qh0));
        __nv_bfloat16 ql1 = __float2bfloat16(qv.y - __bfloat162float(qh1));
        __nv_bfloat16 ql2 = __float2bfloat16(qv.z - __bfloat162float(qh2));
        __nv_bfloat16 ql3 = __float2bfloat16(qv.w - __bfloat162float(qh3));
        __nv_bfloat16 kh0 = __float2bfloat16(kv.x), kh1 = __float2bfloat16(kv.y);
        __nv_bfloat16 kh2 = __float2bfloat16(kv.z), kh3 = __float2bfloat16(kv.w);
        __nv_bfloat16 kl0 = __float2bfloat16(kv.x - __bfloat162float(kh0));
        __nv_bfloat16 kl1 = __float2bfloat16(kv.y - __bfloat162float(kh1));
        __nv_bfloat16 kl2 = __float2bfloat16(kv.z - __bfloat162float(kh2));
        __nv_bfloat16 kl3 = __float2bfloat16(kv.w - __bfloat162float(kh3));

        __nv_bfloat16* ap = As + row * SROW + c4;
        __nv_bfloat16* bp = Bs + row * SROW + c4;
        ap[0] = qh0; ap[1] = qh1; ap[2] = qh2; ap[3] = qh3;
        ap[64] = ql0; ap[65] = ql1; ap[66] = ql2; ap[67] = ql3;
        bp[0] = kh0; bp[1] = kh1; bp[2] = kh2; bp[3] = kh3;
        bp[64] = kl0; bp[65] = kl1; bp[66] = kl2; bp[67] = kl3;
    }
    __syncthreads();

    const uint32_t a_base = smem_u32(As);
    const uint32_t b_base = smem_u32(Bs);

    const int arow  = lane & 15;
    const int akoff = (lane >> 4) * 8;
    const int brow  = lane & 7;
    const int bkoff = ((lane >> 3) & 1) * 8;

    float acc[4][4][4];
#pragma unroll
    for (int mi = 0; mi < 4; mi++)
#pragma unroll
        for (int ni = 0; ni < 4; ni++)
#pragma unroll
            for (int r = 0; r < 4; r++) acc[mi][ni][r] = 0.0f;

#pragma unroll
    for (int s = 0; s < KSTEPS; s++) {
        // split-term block mapping (constant-folded at compile time)
        const int ka = (s < 4) ? s * 16 : (s < 8) ? (s - 4) * 16 : 64 + (s - 8) * 16;
        const int kb = (s < 4) ? s * 16 : (s < 8) ? 64 + (s - 4) * 16 : (s - 8) * 16;

        uint32_t af[4][4], bf[4][2];
#pragma unroll
        for (int mi = 0; mi < 4; mi++) {
            uint32_t addr = a_base + (uint32_t)(((wm + mi * 16 + arow) * SROW + ka + akoff) * 2);
            asm volatile("ldmatrix.sync.aligned.m8n8.x4.shared.b16 {%0,%1,%2,%3}, [%4];"
                         : "=r"(af[mi][0]), "=r"(af[mi][1]), "=r"(af[mi][2]), "=r"(af[mi][3])
                         : "r"(addr));
        }
#pragma unroll
        for (int ni = 0; ni < 4; ni++) {
            uint32_t addr = b_base + (uint32_t)(((wn + ni * 8 + brow) * SROW + kb + bkoff) * 2);
            asm volatile("ldmatrix.sync.aligned.m8n8.x2.shared.b16 {%0,%1}, [%2];"
                         : "=r"(bf[ni][0]), "=r"(bf[ni][1])
                         : "r"(addr));
        }
#pragma unroll
        for (int mi = 0; mi < 4; mi++)
#pragma unroll
            for (int ni = 0; ni < 4; ni++) {
                asm volatile(
                    "mma.sync.aligned.m16n8k16.row.col.f32.bf16.bf16.f32 "
                    "{%0,%1,%2,%3}, {%4,%5,%6,%7}, {%8,%9}, {%0,%1,%2,%3};"
                    : "+f"(acc[mi][ni][0]), "+f"(acc[mi][ni][1]),
                      "+f"(acc[mi][ni][2]), "+f"(acc[mi][ni][3])
                    : "r"(af[mi][0]), "r"(af[mi][1]), "r"(af[mi][2]), "r"(af[mi][3]),
                      "r"(bf[ni][0]), "r"(bf[ni][1]));
            }
    }

    // --- store fp16: (c0,c1)->(m,n), (c2,c3)->(m+8,n) as half2 ---
    __half* __restrict__ Sp = g_S + (size_t)bg * NN;
#pragma unroll
    for (int mi = 0; mi < 4; mi++) {
#pragma unroll
        for (int ni = 0; ni < 4; ni++) {
            int m = qt + wm + mi * 16 + (lane >> 2);
            int n = kt + wn + ni * 8 + (lane & 3) * 2;
            *(__half2*)(Sp + (size_t)m * N_TOK + n) =
                __floats2half2_rn(acc[mi][ni][0], acc[mi][ni][1]);
            *(__half2*)(Sp + (size_t)(m + 8) * N_TOK + n) =
                __floats2half2_rn(acc[mi][ni][2], acc[mi][ni][3]);
        }
    }
}

// ---------------------------------------------------------------------------
// Kernel 2: epilogue. One thread per (q,k); all 8 batches per thread.
// ---------------------------------------------------------------------------
__global__ __launch_bounds__(256, 4)
void epilogue_kernel(const float* __restrict__ masks,
                     const float* __restrict__ proj,
                     const float* __restrict__ hw,
                     const float* __restrict__ hb,
                     float* __restrict__ out)
{
    __shared__ float sP[NLVL * NGH * NLH];
    __shared__ float sW[NLH * NLH];
    __shared__ float sB[NLH];

    const int tid = threadIdx.x;
    if (tid < 128) sP[tid] = proj[tid];
    if (tid < 64)  sW[tid] = hw[tid];
    if (tid < 8)   sB[tid] = hb[tid];
    __syncthreads();

    const size_t i = (size_t)blockIdx.x * 256 + tid;
    float4 m = *(const float4*)(masks + 4 * i);

    float mw[NGH * NLH];
#pragma unroll
    for (int x = 0; x < 32; x++) {
        float t = m.x * sP[x];
        t = fmaf(m.y, sP[32 + x], t);
        t = fmaf(m.z, sP[64 + x], t);
        t = fmaf(m.w, sP[96 + x], t);
        mw[x] = t;
    }

    const __half* __restrict__ Sp = g_S + i;

#pragma unroll
    for (int b = 0; b < NB; b++) {
        float s0 = __half2float(Sp[((size_t)(b * 4 + 0)) << 20]);
        float s1 = __half2float(Sp[((size_t)(b * 4 + 1)) << 20]);
        float s2 = __half2float(Sp[((size_t)(b * 4 + 2)) << 20]);
        float s3 = __half2float(Sp[((size_t)(b * 4 + 3)) << 20]);

        float v[NLH];
#pragma unroll
        for (int h = 0; h < NLH; h++) {
            float t = s0 * mw[h];
            t = fmaf(s1, mw[8 + h], t);
            t = fmaf(s2, mw[16 + h], t);
            t = fmaf(s3, mw[24 + h], t);
            v[h] = fmaxf(t, 0.0f);
        }
#pragma unroll
        for (int h = 0; h < NLH; h++) {
            float o = sB[h];
#pragma unroll
            for (int hh = 0; hh < NLH; hh++)
                o = fmaf(v[hh], sW[h * 8 + hh], o);
            out[((size_t)(b * 8 + h) << 20) + i] = o;
        }
    }
}

extern "C" void kernel_launch(void* const* d_in, const int* in_sizes, int n_in,
                              void* d_out, int out_size)
{
    const float* q     = (const float*)d_in[0];
    const float* k     = (const float*)d_in[1];
    const float* masks = (const float*)d_in[2];
    const float* proj  = (const float*)d_in[3];
    const float* hw    = (const float*)d_in[4];
    const float* hb    = (const float*)d_in[5];
    float* out = (float*)d_out;

    cudaFuncSetAttribute(qk_gemm_mma, cudaFuncAttributeMaxDynamicSharedMemorySize, SM_BYTES);

    dim3 g1(N_TOK / 128, N_TOK / 128, NBG);
    qk_gemm_mma<<<g1, 256, SM_BYTES>>>(q, k);

    epilogue_kernel<<<NN / 256, 256>>>(masks, proj, hw, hb, out);
}